// round 6
// baseline (speedup 1.0000x reference)
#include <cuda_runtime.h>
#include <cuda_bf16.h>

// emdModule: brute-force NN (min/argmin over pairwise Euclidean distances)
// + 50-step price recurrence. Single fused kernel, 4 threads per row,
// group-of-8 tournament argmin with deferred replay.
//
// Rounding model (BIT-EXACT vs the JAX reference):
//   inner = fma(z,c, fma(y,b, x*a))        (XLA dot contraction, FMA chain)
//   d2    = fma(-2, inner, sq1 + sq2)      == (sq1+sq2) - 2*inner exactly
//   sq    = (x*x + y*y) + z*z              (elementwise squares, no fma)
//   cost  = sqrt(max(d2,0)) — monotone => min/argmin over raw d2
//   argmin: first index. Groups scanned ascending with strict < on the exact
//   group min; winning group replayed, first candidate == gmin wins. This is
//   exactly first-index argmin. Cross-thread merge via packed
//   (bits(d2)<<32 | j) u64 min.
//   price recurrence: m = c_min - price; price += eps*m (separate rounded ops)

#define BATCH 16
#define NPTS 2048
#define ITILE 128                  // rows per block
#define TPB 512                    // 4 threads per row (one per j-quarter)
#define NQUARTER 4
#define NPAIRS (NPTS / 2)          // 1024 packed candidate pairs
#define QPAIRS (NPAIRS / NQUARTER) // 256 pairs per thread
#define GPAIRS 4                   // pairs per tournament group (8 candidates)
#define NGROUP (QPAIRS / GPAIRS)   // 64 groups per thread
#define ITILES (NPTS / ITILE)      // 16
#define ROWS (BATCH * NPTS)        // 32768

typedef unsigned long long u64;

__device__ __forceinline__ u64 pk2(float lo, float hi) {
    u64 r; asm("mov.b64 %0, {%1, %2};" : "=l"(r) : "f"(lo), "f"(hi)); return r;
}
__device__ __forceinline__ float lo2(u64 v) {
    return __uint_as_float((unsigned)v);          // low register half (free)
}
__device__ __forceinline__ float hi2(u64 v) {
    return __uint_as_float((unsigned)(v >> 32));  // high register half (free)
}
__device__ __forceinline__ u64 mul2(u64 a, u64 b) {
    u64 d; asm("mul.rn.f32x2 %0, %1, %2;" : "=l"(d) : "l"(a), "l"(b)); return d;
}
__device__ __forceinline__ u64 add2(u64 a, u64 b) {
    u64 d; asm("add.rn.f32x2 %0, %1, %2;" : "=l"(d) : "l"(a), "l"(b)); return d;
}
__device__ __forceinline__ u64 fma2(u64 a, u64 b, u64 c) {
    u64 d; asm("fma.rn.f32x2 %0, %1, %2, %3;" : "=l"(d) : "l"(a), "l"(b), "l"(c));
    return d;
}

__global__ void __launch_bounds__(TPB, 2) emd_fused_kernel(
    const float* __restrict__ x1, const float* __restrict__ x2,
    float* __restrict__ out,
    const float* __restrict__ eps_p, const int* __restrict__ iters_p,
    int write_assign) {
    int blk = blockIdx.x;
    int b   = blk / ITILES;           // batch
    int it  = blk % ITILES;           // i-tile

    // Pre-packed pair-SoA staging of the FULL x2 set for this batch:
    //   tab_ab[p] = { pack(a0,a1), pack(b0,b1) }
    //   tab_cw[p] = { pack(c0,c1), pack(w0,w1) }
    // LDS.128 loads both packed 64-bit operands (broadcast, conflict-free).
    __shared__ ulonglong2 tab_ab[NPAIRS];
    __shared__ ulonglong2 tab_cw[NPAIRS];
    __shared__ u64 part[TPB];

    int tid   = threadIdx.x;
    int row_l = tid & (ITILE - 1);    // row within tile (0..127)
    int q     = tid >> 7;             // j-quarter (0..3)

    const float* p2 = x2 + (long)b * NPTS * 3;
    for (int p = tid; p < NPAIRS; p += TPB) {
        float a0 = p2[6 * p + 0], b0 = p2[6 * p + 1], c0 = p2[6 * p + 2];
        float a1 = p2[6 * p + 3], b1 = p2[6 * p + 4], c1 = p2[6 * p + 5];
        float w0 = __fadd_rn(__fadd_rn(__fmul_rn(a0, a0), __fmul_rn(b0, b0)),
                             __fmul_rn(c0, c0));
        float w1 = __fadd_rn(__fadd_rn(__fmul_rn(a1, a1), __fmul_rn(b1, b1)),
                             __fmul_rn(c1, c1));
        tab_ab[p] = make_ulonglong2(pk2(a0, a1), pk2(b0, b1));
        tab_cw[p] = make_ulonglong2(pk2(c0, c1), pk2(w0, w1));
    }
    __syncthreads();

    int i = it * ITILE + row_l;
    const float* p1 = x1 + ((long)b * NPTS + i) * 3;
    float x = p1[0], y = p1[1], z = p1[2];
    float sq1 = __fadd_rn(__fadd_rn(__fmul_rn(x, x), __fmul_rn(y, y)),
                          __fmul_rn(z, z));

    u64 x2p = pk2(x, x), y2p = pk2(y, y), z2p = pk2(z, z);
    u64 s2p = pk2(sq1, sq1);
    u64 m2p = pk2(-2.0f, -2.0f);

    // d2 for packed pair p (both lanes bit-exact vs reference).
    auto dist2 = [&](int p) -> u64 {
        ulonglong2 ab = tab_ab[p];
        ulonglong2 cw = tab_cw[p];
        u64 inner2 = fma2(z2p, cw.x, fma2(y2p, ab.y, mul2(x2p, ab.x)));
        return fma2(m2p, inner2, add2(s2p, cw.y));
    };

    // Tournament: exact min per group of 8 candidates; ONE update per group.
    int   p0   = q * QPAIRS;
    float best = 3.4028235e38f;
    int   bg   = 0;
    #pragma unroll 2
    for (int g = 0; g < NGROUP; g++) {
        int p = p0 + g * GPAIRS;
        u64 d0 = dist2(p + 0);
        u64 d1 = dist2(p + 1);
        u64 d2v = dist2(p + 2);
        u64 d3 = dist2(p + 3);
        float m0 = fminf(lo2(d0), hi2(d0));
        float m1 = fminf(lo2(d1), hi2(d1));
        float m2 = fminf(lo2(d2v), hi2(d2v));
        float m3 = fminf(lo2(d3), hi2(d3));
        float gmin = fminf(fminf(m0, m1), fminf(m2, m3));
        if (gmin < best) { best = gmin; bg = g; }  // strict <: earliest group
    }

    // Replay the winning group (exact recompute): first candidate == best.
    int bj = 0;
    {
        bool found = false;
        int pb = p0 + bg * GPAIRS;
        #pragma unroll
        for (int k = 0; k < GPAIRS; k++) {
            u64 d = dist2(pb + k);
            float dl = lo2(d), dh = hi2(d);
            if (!found && dl == best) { bj = 2 * (pb + k);     found = true; }
            if (!found && dh == best) { bj = 2 * (pb + k) + 1; found = true; }
        }
    }

    // Clamp only the row minimum (commutes with min); pack for cross-thread
    // merge: positive-float bit order == value order, low j bits break ties
    // toward the first index.
    float dmin = fmaxf(best, 0.0f);
    part[tid] = ((u64)__float_as_uint(dmin) << 32) | (unsigned)bj;
    __syncthreads();

    // Threads 0..127: merge 4 quarter-partials for their row + epilogue.
    if (tid < ITILE) {
        u64 key = part[tid];
        #pragma unroll
        for (int qq = 1; qq < NQUARTER; qq++) {
            u64 k2 = part[qq * ITILE + tid];
            if (k2 < key) key = k2;
        }
        float d2 = __uint_as_float((unsigned)(key >> 32));
        int   aj = (int)(key & 0xFFFFFFFFu);

        float cmin = sqrtf(d2);                          // IEEE sqrt (d2 >= 0)
        float eps  = eps_p   ? *eps_p   : 0.005f;
        int   iters = iters_p ? *iters_p : 50;

        float price = 0.0f;
        float m = 0.0f;
        for (int t = 0; t < iters; t++) {
            m = __fadd_rn(cmin, -price);                 // c_min - price
            price = __fadd_rn(price, __fmul_rn(eps, m)); // price += eps*m
        }

        int row = b * NPTS + i;
        out[row] = sqrtf(m);
        if (write_assign) out[ROWS + row] = (float)aj;
    }
}

extern "C" void kernel_launch(void* const* d_in, const int* in_sizes, int n_in,
                              void* d_out, int out_size) {
    const float* x1 = (const float*)d_in[0];
    const float* x2 = (const float*)d_in[1];
    const float* eps_p   = (n_in > 2) ? (const float*)d_in[2] : nullptr;
    const int*   iters_p = (n_in > 3) ? (const int*)d_in[3]   : nullptr;

    int write_assign = (out_size >= 2 * ROWS) ? 1 : 0;
    emd_fused_kernel<<<BATCH * ITILES, TPB>>>(x1, x2, (float*)d_out,
                                              eps_p, iters_p, write_assign);
}

// round 7
// speedup vs baseline: 1.0708x; 1.0708x over previous
#include <cuda_runtime.h>
#include <cuda_bf16.h>

// emdModule: brute-force NN (min/argmin over pairwise Euclidean distances)
// + 50-step price recurrence. Single fused kernel.
// 2 rows per thread (amortizes each candidate LDS over 2 query rows),
// group-of-8 tournament argmin with deferred replay.
//
// Rounding model (BIT-EXACT vs the JAX reference):
//   inner = fma(z,c, fma(y,b, x*a))        (XLA dot contraction, FMA chain)
//   d2    = fma(-2, inner, sq1 + sq2)      == (sq1+sq2) - 2*inner exactly
//   sq    = (x*x + y*y) + z*z              (elementwise squares, no fma)
//   cost  = sqrt(max(d2,0)) — monotone => min/argmin over raw d2
//   argmin: first index. Groups scanned ascending with strict < on the exact
//   group min; winning group replayed, first candidate == gmin wins.
//   Cross-slice merge via packed (bits(d2)<<32 | j) u64 min.
//   price recurrence: m = c_min - price; price += eps*m (separate rounded ops)

#define BATCH 16
#define NPTS 2048
#define ITILE 128                  // rows per block
#define TPB 512
#define RPT 2                      // rows per thread
#define RSLOTS (ITILE / RPT)       // 64 row-slots
#define NSLICE (TPB / RSLOTS)      // 8 j-slices
#define NPAIRS (NPTS / 2)          // 1024 packed candidate pairs
#define SPAIRS (NPAIRS / NSLICE)   // 128 pairs per slice
#define GPAIRS 4                   // pairs per tournament group (8 candidates)
#define NGROUP (SPAIRS / GPAIRS)   // 32 groups per slice
#define ITILES (NPTS / ITILE)      // 16
#define ROWS (BATCH * NPTS)        // 32768

typedef unsigned long long u64;

__device__ __forceinline__ u64 pk2(float lo, float hi) {
    u64 r; asm("mov.b64 %0, {%1, %2};" : "=l"(r) : "f"(lo), "f"(hi)); return r;
}
__device__ __forceinline__ float lo2(u64 v) {
    return __uint_as_float((unsigned)v);          // low register half (free)
}
__device__ __forceinline__ float hi2(u64 v) {
    return __uint_as_float((unsigned)(v >> 32));  // high register half (free)
}
__device__ __forceinline__ u64 mul2(u64 a, u64 b) {
    u64 d; asm("mul.rn.f32x2 %0, %1, %2;" : "=l"(d) : "l"(a), "l"(b)); return d;
}
__device__ __forceinline__ u64 add2(u64 a, u64 b) {
    u64 d; asm("add.rn.f32x2 %0, %1, %2;" : "=l"(d) : "l"(a), "l"(b)); return d;
}
__device__ __forceinline__ u64 fma2(u64 a, u64 b, u64 c) {
    u64 d; asm("fma.rn.f32x2 %0, %1, %2, %3;" : "=l"(d) : "l"(a), "l"(b), "l"(c));
    return d;
}

__global__ void __launch_bounds__(TPB, 2) emd_fused_kernel(
    const float* __restrict__ x1, const float* __restrict__ x2,
    float* __restrict__ out,
    const float* __restrict__ eps_p, const int* __restrict__ iters_p,
    int write_assign) {
    int blk = blockIdx.x;
    int b   = blk / ITILES;           // batch
    int it  = blk % ITILES;           // i-tile

    // Pre-packed pair-SoA staging of the FULL x2 set for this batch:
    //   tab_ab[p] = { pack(a0,a1), pack(b0,b1) }
    //   tab_cw[p] = { pack(c0,c1), pack(w0,w1) }
    __shared__ ulonglong2 tab_ab[NPAIRS];
    __shared__ ulonglong2 tab_cw[NPAIRS];
    __shared__ u64 part[NSLICE * ITILE];

    int tid = threadIdx.x;
    int rs  = tid & (RSLOTS - 1);     // row slot (0..63)
    int q   = tid >> 6;               // j-slice (0..7)

    const float* p2 = x2 + (long)b * NPTS * 3;
    for (int p = tid; p < NPAIRS; p += TPB) {
        float a0 = p2[6 * p + 0], b0 = p2[6 * p + 1], c0 = p2[6 * p + 2];
        float a1 = p2[6 * p + 3], b1 = p2[6 * p + 4], c1 = p2[6 * p + 5];
        float w0 = __fadd_rn(__fadd_rn(__fmul_rn(a0, a0), __fmul_rn(b0, b0)),
                             __fmul_rn(c0, c0));
        float w1 = __fadd_rn(__fadd_rn(__fmul_rn(a1, a1), __fmul_rn(b1, b1)),
                             __fmul_rn(c1, c1));
        tab_ab[p] = make_ulonglong2(pk2(a0, a1), pk2(b0, b1));
        tab_cw[p] = make_ulonglong2(pk2(c0, c1), pk2(w0, w1));
    }
    __syncthreads();

    // Two query rows per thread: rows rs and rs+64 of this tile.
    int i0 = it * ITILE + rs;
    int i1 = i0 + RSLOTS;
    const float* pr0 = x1 + ((long)b * NPTS + i0) * 3;
    const float* pr1 = x1 + ((long)b * NPTS + i1) * 3;
    float xA = pr0[0], yA = pr0[1], zA = pr0[2];
    float xB = pr1[0], yB = pr1[1], zB = pr1[2];
    float sqA = __fadd_rn(__fadd_rn(__fmul_rn(xA, xA), __fmul_rn(yA, yA)),
                          __fmul_rn(zA, zA));
    float sqB = __fadd_rn(__fadd_rn(__fmul_rn(xB, xB), __fmul_rn(yB, yB)),
                          __fmul_rn(zB, zB));

    u64 xA2 = pk2(xA, xA), yA2 = pk2(yA, yA), zA2 = pk2(zA, zA), sA2 = pk2(sqA, sqA);
    u64 xB2 = pk2(xB, xB), yB2 = pk2(yB, yB), zB2 = pk2(zB, zB), sB2 = pk2(sqB, sqB);
    u64 m2p = pk2(-2.0f, -2.0f);

    int p0 = q * SPAIRS;
    float bestA = 3.4028235e38f, bestB = 3.4028235e38f;
    int   bgA = 0, bgB = 0;

    #pragma unroll 2
    for (int g = 0; g < NGROUP; g++) {
        int p = p0 + g * GPAIRS;
        // One LDS stream feeds BOTH rows' FMA chains (2x arithmetic per load).
        ulonglong2 ab0 = tab_ab[p + 0], cw0 = tab_cw[p + 0];
        ulonglong2 ab1 = tab_ab[p + 1], cw1 = tab_cw[p + 1];
        ulonglong2 ab2 = tab_ab[p + 2], cw2 = tab_cw[p + 2];
        ulonglong2 ab3 = tab_ab[p + 3], cw3 = tab_cw[p + 3];

        // Row A
        u64 dA0 = fma2(m2p, fma2(zA2, cw0.x, fma2(yA2, ab0.y, mul2(xA2, ab0.x))), add2(sA2, cw0.y));
        u64 dA1 = fma2(m2p, fma2(zA2, cw1.x, fma2(yA2, ab1.y, mul2(xA2, ab1.x))), add2(sA2, cw1.y));
        u64 dA2 = fma2(m2p, fma2(zA2, cw2.x, fma2(yA2, ab2.y, mul2(xA2, ab2.x))), add2(sA2, cw2.y));
        u64 dA3 = fma2(m2p, fma2(zA2, cw3.x, fma2(yA2, ab3.y, mul2(xA2, ab3.x))), add2(sA2, cw3.y));
        float gA = fminf(fminf(fminf(lo2(dA0), hi2(dA0)), fminf(lo2(dA1), hi2(dA1))),
                         fminf(fminf(lo2(dA2), hi2(dA2)), fminf(lo2(dA3), hi2(dA3))));
        if (gA < bestA) { bestA = gA; bgA = g; }   // strict <: earliest group

        // Row B
        u64 dB0 = fma2(m2p, fma2(zB2, cw0.x, fma2(yB2, ab0.y, mul2(xB2, ab0.x))), add2(sB2, cw0.y));
        u64 dB1 = fma2(m2p, fma2(zB2, cw1.x, fma2(yB2, ab1.y, mul2(xB2, ab1.x))), add2(sB2, cw1.y));
        u64 dB2 = fma2(m2p, fma2(zB2, cw2.x, fma2(yB2, ab2.y, mul2(xB2, ab2.x))), add2(sB2, cw2.y));
        u64 dB3 = fma2(m2p, fma2(zB2, cw3.x, fma2(yB2, ab3.y, mul2(xB2, ab3.x))), add2(sB2, cw3.y));
        float gB = fminf(fminf(fminf(lo2(dB0), hi2(dB0)), fminf(lo2(dB1), hi2(dB1))),
                         fminf(fminf(lo2(dB2), hi2(dB2)), fminf(lo2(dB3), hi2(dB3))));
        if (gB < bestB) { bestB = gB; bgB = g; }
    }

    // Replay winning group per row (exact recompute): first candidate == best.
    auto replay = [&](u64 xq, u64 yq, u64 zq, u64 sq, float best, int bg) -> int {
        int bj = 0;
        bool found = false;
        int pb = p0 + bg * GPAIRS;
        #pragma unroll
        for (int k = 0; k < GPAIRS; k++) {
            ulonglong2 ab = tab_ab[pb + k];
            ulonglong2 cw = tab_cw[pb + k];
            u64 d = fma2(m2p, fma2(zq, cw.x, fma2(yq, ab.y, mul2(xq, ab.x))),
                         add2(sq, cw.y));
            float dl = lo2(d), dh = hi2(d);
            if (!found && dl == best) { bj = 2 * (pb + k);     found = true; }
            if (!found && dh == best) { bj = 2 * (pb + k) + 1; found = true; }
        }
        return bj;
    };
    int bjA = replay(xA2, yA2, zA2, sA2, bestA, bgA);
    int bjB = replay(xB2, yB2, zB2, sB2, bestB, bgB);

    // Clamp row minima (commutes with min); pack (bits<<32|j): positive-float
    // bit order == value order; low j bits break ties toward first index.
    part[q * ITILE + rs]          =
        ((u64)__float_as_uint(fmaxf(bestA, 0.0f)) << 32) | (unsigned)bjA;
    part[q * ITILE + rs + RSLOTS] =
        ((u64)__float_as_uint(fmaxf(bestB, 0.0f)) << 32) | (unsigned)bjB;
    __syncthreads();

    // Threads 0..127: merge the 8 slice-partials for their row + epilogue.
    if (tid < ITILE) {
        u64 key = part[tid];
        #pragma unroll
        for (int s = 1; s < NSLICE; s++) {
            u64 k2 = part[s * ITILE + tid];
            if (k2 < key) key = k2;
        }
        float d2 = __uint_as_float((unsigned)(key >> 32));
        int   aj = (int)(key & 0xFFFFFFFFu);

        float cmin = sqrtf(d2);                          // IEEE sqrt (d2 >= 0)
        float eps  = eps_p   ? *eps_p   : 0.005f;
        int   iters = iters_p ? *iters_p : 50;

        float price = 0.0f;
        float m = 0.0f;
        for (int t = 0; t < iters; t++) {
            m = __fadd_rn(cmin, -price);                 // c_min - price
            price = __fadd_rn(price, __fmul_rn(eps, m)); // price += eps*m
        }

        int row = b * NPTS + it * ITILE + tid;
        out[row] = sqrtf(m);
        if (write_assign) out[ROWS + row] = (float)aj;
    }
}

extern "C" void kernel_launch(void* const* d_in, const int* in_sizes, int n_in,
                              void* d_out, int out_size) {
    const float* x1 = (const float*)d_in[0];
    const float* x2 = (const float*)d_in[1];
    const float* eps_p   = (n_in > 2) ? (const float*)d_in[2] : nullptr;
    const int*   iters_p = (n_in > 3) ? (const int*)d_in[3]   : nullptr;

    int write_assign = (out_size >= 2 * ROWS) ? 1 : 0;
    emd_fused_kernel<<<BATCH * ITILES, TPB>>>(x1, x2, (float*)d_out,
                                              eps_p, iters_p, write_assign);
}

// round 8
// speedup vs baseline: 1.0804x; 1.0089x over previous
#include <cuda_runtime.h>
#include <cuda_bf16.h>

// emdModule: brute-force NN (min/argmin over pairwise Euclidean distances)
// + 50-step price recurrence. Single fused kernel.
// 4 rows per thread (each candidate LDS feeds 4 independent FMA chains),
// group-of-8 tournament with running-min accumulators + deferred replay.
//
// Rounding model (BIT-EXACT vs the JAX reference):
//   inner = fma(z,c, fma(y,b, x*a))        (XLA dot contraction, FMA chain)
//   d2    = fma(-2, inner, sq1 + sq2)      == (sq1+sq2) - 2*inner exactly
//   sq    = (x*x + y*y) + z*z              (elementwise squares, no fma)
//   cost  = sqrt(max(d2,0)) — monotone => min/argmin over raw d2
//   argmin: first index. Groups scanned ascending, strict < on exact group
//   min; winning group replayed, first candidate == gmin wins.
//   Cross-slice merge via packed (bits(d2)<<32 | j) u64 min.
//   price recurrence: m = c_min - price; price += eps*m (separate rounded ops)

#define BATCH 16
#define NPTS 2048
#define ITILE 128                  // rows per block
#define TPB 512
#define RPT 4                      // rows per thread
#define RSLOTS (ITILE / RPT)       // 32 row-slots (= lane id)
#define NSLICE (TPB / RSLOTS)      // 16 j-slices (= warp id)
#define NPAIRS (NPTS / 2)          // 1024 packed candidate pairs
#define SPAIRS (NPAIRS / NSLICE)   // 64 pairs per slice
#define GPAIRS 4                   // pairs per tournament group (8 candidates)
#define NGROUP (SPAIRS / GPAIRS)   // 16 groups per slice
#define ITILES (NPTS / ITILE)      // 16
#define ROWS (BATCH * NPTS)        // 32768

typedef unsigned long long u64;

__device__ __forceinline__ u64 pk2(float lo, float hi) {
    u64 r; asm("mov.b64 %0, {%1, %2};" : "=l"(r) : "f"(lo), "f"(hi)); return r;
}
__device__ __forceinline__ float lo2(u64 v) {
    return __uint_as_float((unsigned)v);          // low register half (free)
}
__device__ __forceinline__ float hi2(u64 v) {
    return __uint_as_float((unsigned)(v >> 32));  // high register half (free)
}
__device__ __forceinline__ u64 mul2(u64 a, u64 b) {
    u64 d; asm("mul.rn.f32x2 %0, %1, %2;" : "=l"(d) : "l"(a), "l"(b)); return d;
}
__device__ __forceinline__ u64 add2(u64 a, u64 b) {
    u64 d; asm("add.rn.f32x2 %0, %1, %2;" : "=l"(d) : "l"(a), "l"(b)); return d;
}
__device__ __forceinline__ u64 fma2(u64 a, u64 b, u64 c) {
    u64 d; asm("fma.rn.f32x2 %0, %1, %2, %3;" : "=l"(d) : "l"(a), "l"(b), "l"(c));
    return d;
}

__global__ void __launch_bounds__(TPB, 2) emd_fused_kernel(
    const float* __restrict__ x1, const float* __restrict__ x2,
    float* __restrict__ out,
    const float* __restrict__ eps_p, const int* __restrict__ iters_p,
    int write_assign) {
    int blk = blockIdx.x;
    int b   = blk / ITILES;           // batch
    int it  = blk % ITILES;           // i-tile

    // Pre-packed pair-SoA staging of the FULL x2 set for this batch:
    //   tab_ab[p] = { pack(a0,a1), pack(b0,b1) }
    //   tab_cw[p] = { pack(c0,c1), pack(w0,w1) }
    __shared__ ulonglong2 tab_ab[NPAIRS];
    __shared__ ulonglong2 tab_cw[NPAIRS];
    __shared__ u64 part[NSLICE * ITILE];

    int tid = threadIdx.x;
    int rs  = tid & (RSLOTS - 1);     // row slot (0..31) == lane
    int q   = tid >> 5;               // j-slice (0..15) == warp

    const float* p2 = x2 + (long)b * NPTS * 3;
    for (int p = tid; p < NPAIRS; p += TPB) {
        float a0 = p2[6 * p + 0], b0 = p2[6 * p + 1], c0 = p2[6 * p + 2];
        float a1 = p2[6 * p + 3], b1 = p2[6 * p + 4], c1 = p2[6 * p + 5];
        float w0 = __fadd_rn(__fadd_rn(__fmul_rn(a0, a0), __fmul_rn(b0, b0)),
                             __fmul_rn(c0, c0));
        float w1 = __fadd_rn(__fadd_rn(__fmul_rn(a1, a1), __fmul_rn(b1, b1)),
                             __fmul_rn(c1, c1));
        tab_ab[p] = make_ulonglong2(pk2(a0, a1), pk2(b0, b1));
        tab_cw[p] = make_ulonglong2(pk2(c0, c1), pk2(w0, w1));
    }
    __syncthreads();

    // Four query rows per thread: rows rs + r*32 of this tile.
    u64 xq[RPT], yq[RPT], zq[RPT], sq[RPT];
    #pragma unroll
    for (int r = 0; r < RPT; r++) {
        int i = it * ITILE + rs + r * RSLOTS;
        const float* pr = x1 + ((long)b * NPTS + i) * 3;
        float x = pr[0], y = pr[1], z = pr[2];
        float s = __fadd_rn(__fadd_rn(__fmul_rn(x, x), __fmul_rn(y, y)),
                            __fmul_rn(z, z));
        xq[r] = pk2(x, x); yq[r] = pk2(y, y); zq[r] = pk2(z, z);
        sq[r] = pk2(s, s);
    }
    u64 m2p = pk2(-2.0f, -2.0f);

    int p0 = q * SPAIRS;
    float best[RPT];
    int   bg[RPT];
    #pragma unroll
    for (int r = 0; r < RPT; r++) { best[r] = 3.4028235e38f; bg[r] = 0; }

    for (int g = 0; g < NGROUP; g++) {
        int p = p0 + g * GPAIRS;
        float gmin[RPT];
        #pragma unroll
        for (int r = 0; r < RPT; r++) gmin[r] = 3.4028235e38f;

        #pragma unroll
        for (int k = 0; k < GPAIRS; k++) {
            ulonglong2 ab = tab_ab[p + k];   // one LDS pair feeds 4 rows
            ulonglong2 cw = tab_cw[p + k];
            #pragma unroll
            for (int r = 0; r < RPT; r++) {
                u64 inner2 = fma2(zq[r], cw.x,
                                  fma2(yq[r], ab.y, mul2(xq[r], ab.x)));
                u64 d = fma2(m2p, inner2, add2(sq[r], cw.y));
                gmin[r] = fminf(gmin[r], fminf(lo2(d), hi2(d)));
            }
        }
        #pragma unroll
        for (int r = 0; r < RPT; r++) {
            if (gmin[r] < best[r]) { best[r] = gmin[r]; bg[r] = g; }
        }
    }

    // Replay winning group per row (exact recompute): first candidate == best.
    int bj[RPT];
    #pragma unroll
    for (int r = 0; r < RPT; r++) {
        int pb = p0 + bg[r] * GPAIRS;
        int bjr = 0;
        bool found = false;
        #pragma unroll
        for (int k = 0; k < GPAIRS; k++) {
            ulonglong2 ab = tab_ab[pb + k];
            ulonglong2 cw = tab_cw[pb + k];
            u64 d = fma2(m2p,
                         fma2(zq[r], cw.x, fma2(yq[r], ab.y, mul2(xq[r], ab.x))),
                         add2(sq[r], cw.y));
            float dl = lo2(d), dh = hi2(d);
            if (!found && dl == best[r]) { bjr = 2 * (pb + k);     found = true; }
            if (!found && dh == best[r]) { bjr = 2 * (pb + k) + 1; found = true; }
        }
        bj[r] = bjr;
    }

    // Clamp row minima (commutes with min); pack (bits<<32|j): positive-float
    // bit order == value order; low j bits break ties toward first index.
    #pragma unroll
    for (int r = 0; r < RPT; r++) {
        part[q * ITILE + rs + r * RSLOTS] =
            ((u64)__float_as_uint(fmaxf(best[r], 0.0f)) << 32) | (unsigned)bj[r];
    }
    __syncthreads();

    // Threads 0..127: merge the 16 slice-partials for their row + epilogue.
    if (tid < ITILE) {
        u64 key = part[tid];
        #pragma unroll
        for (int s = 1; s < NSLICE; s++) {
            u64 k2 = part[s * ITILE + tid];
            if (k2 < key) key = k2;
        }
        float d2 = __uint_as_float((unsigned)(key >> 32));
        int   aj = (int)(key & 0xFFFFFFFFu);

        float cmin = sqrtf(d2);                          // IEEE sqrt (d2 >= 0)
        float eps  = eps_p   ? *eps_p   : 0.005f;
        int   iters = iters_p ? *iters_p : 50;

        float price = 0.0f;
        float m = 0.0f;
        for (int t = 0; t < iters; t++) {
            m = __fadd_rn(cmin, -price);                 // c_min - price
            price = __fadd_rn(price, __fmul_rn(eps, m)); // price += eps*m
        }

        int row = b * NPTS + it * ITILE + tid;
        out[row] = sqrtf(m);
        if (write_assign) out[ROWS + row] = (float)aj;
    }
}

extern "C" void kernel_launch(void* const* d_in, const int* in_sizes, int n_in,
                              void* d_out, int out_size) {
    const float* x1 = (const float*)d_in[0];
    const float* x2 = (const float*)d_in[1];
    const float* eps_p   = (n_in > 2) ? (const float*)d_in[2] : nullptr;
    const int*   iters_p = (n_in > 3) ? (const int*)d_in[3]   : nullptr;

    int write_assign = (out_size >= 2 * ROWS) ? 1 : 0;
    emd_fused_kernel<<<BATCH * ITILES, TPB>>>(x1, x2, (float*)d_out,
                                              eps_p, iters_p, write_assign);
}